// round 12
// baseline (speedup 1.0000x reference)
#include <cuda_runtime.h>

// Problem constants
#define NB   16      // batch
#define NC   64      // channels
#define NH   48      // H == W
#define ND   3072    // xLSTM feature dim (C*W)
#define ND4  12288   // 4*D
#define NT   48      // sequence length
#define NROWS 768    // B*T

// ---------------- device scratch (no allocations allowed) ----------------
__device__ float d_pre1[NROWS * ND4];     // 37.75 MB
__device__ float d_pre2[NROWS * ND4];     // 37.75 MB
__device__ float d_gTp[2 * 2 * ND4 * NB]; // [khalf][stack][col][b] partial h@R
__device__ float d_cst[2 * ND * NB];      // [stack][d][b]
__device__ float d_nst[2 * ND * NB];
__device__ float d_mst[2 * ND * NB];
__device__ float d_hT[2 * ND * NB];       // [stack][d][b]
__device__ float d_Y1[NROWS * ND];        // hidden outputs stack 1 [b][t][d]
__device__ float d_Y2[NROWS * ND];        // hidden outputs stack 2
__device__ float d_xh[NB * NC * NH];
__device__ float d_xw[NB * NC * NH];
__device__ float d_sh[NB * NC * NH];
__device__ float d_sw[NB * NC * NH];

// ---------------- packed fp32x2 helpers (Blackwell FFMA2) ----------------
__device__ __forceinline__ unsigned long long pack2(float x, float y) {
    unsigned long long r;
    asm("mov.b64 %0, {%1, %2};" : "=l"(r) : "f"(x), "f"(y));
    return r;
}
__device__ __forceinline__ void fma2(unsigned long long& c, unsigned long long a,
                                     unsigned long long b) {
    asm("fma.rn.f32x2 %0, %1, %2, %0;" : "+l"(c) : "l"(a), "l"(b));
}
__device__ __forceinline__ float2 unpack2(unsigned long long v) {
    float2 f;
    asm("mov.b64 {%0, %1}, %2;" : "=f"(f.x), "=f"(f.y) : "l"(v));
    return f;
}

// ---------------- pre-projection GEMM: pre = X @ W + bias ----------------
// A: [768, 3072] (x viewed flat), W: [3072, 12288], out: [768, 12288]
// 128x128 tile, BK=8, 256 threads, 8x8 microtile via FFMA2.
__global__ void __launch_bounds__(256) sgemm_pre(const float* __restrict__ A,
                                                 const float* __restrict__ Wm,
                                                 const float* __restrict__ bias,
                                                 int which) {
    __shared__ float As[8][128];
    __shared__ float Bs[8][128];
    float* Cout = which ? d_pre2 : d_pre1;

    int tid = threadIdx.x;
    int bm = blockIdx.y, bn = blockIdx.x;
    int arow = tid >> 1, acol = (tid & 1) << 2;
    int brow = tid >> 5, bcol = (tid & 31) << 2;
    int ty = tid >> 4, tx = tid & 15;

    unsigned long long acc[8][4];
#pragma unroll
    for (int i = 0; i < 8; i++)
#pragma unroll
        for (int j = 0; j < 4; j++) acc[i][j] = 0ull;

    const float* Ap = A + (bm * 128 + arow) * ND + acol;
    const float* Bp = Wm + brow * ND4 + bn * 128 + bcol;

    for (int k0 = 0; k0 < ND; k0 += 8) {
        float4 av = *(const float4*)(Ap + k0);
        float4 bv = *(const float4*)(Bp + (size_t)k0 * ND4);
        As[acol + 0][arow] = av.x;
        As[acol + 1][arow] = av.y;
        As[acol + 2][arow] = av.z;
        As[acol + 3][arow] = av.w;
        *(float4*)&Bs[brow][bcol] = bv;
        __syncthreads();
#pragma unroll
        for (int kk = 0; kk < 8; kk++) {
            float4 a0 = *(const float4*)&As[kk][ty * 8];
            float4 a1 = *(const float4*)&As[kk][ty * 8 + 4];
            ulonglong2 bq0 = *(const ulonglong2*)&Bs[kk][tx * 8];
            ulonglong2 bq1 = *(const ulonglong2*)&Bs[kk][tx * 8 + 4];
            unsigned long long rb[4] = {bq0.x, bq0.y, bq1.x, bq1.y};
            float aa[8] = {a0.x, a0.y, a0.z, a0.w, a1.x, a1.y, a1.z, a1.w};
#pragma unroll
            for (int i = 0; i < 8; i++) {
                unsigned long long ra = pack2(aa[i], aa[i]);
#pragma unroll
                for (int j = 0; j < 4; j++) fma2(acc[i][j], ra, rb[j]);
            }
        }
        __syncthreads();
    }

    int cbase = bn * 128 + tx * 8;
    float4 bb0 = *(const float4*)(bias + cbase);
    float4 bb1 = *(const float4*)(bias + cbase + 4);
#pragma unroll
    for (int i = 0; i < 8; i++) {
        int row = bm * 128 + ty * 8 + i;
        float2 v0 = unpack2(acc[i][0]);
        float2 v1 = unpack2(acc[i][1]);
        float2 v2 = unpack2(acc[i][2]);
        float2 v3 = unpack2(acc[i][3]);
        float4 o0 = make_float4(v0.x + bb0.x, v0.y + bb0.y, v1.x + bb0.z, v1.y + bb0.w);
        float4 o1 = make_float4(v2.x + bb1.x, v2.y + bb1.y, v3.x + bb1.z, v3.y + bb1.w);
        *(float4*)(Cout + (size_t)row * ND4 + cbase) = o0;
        *(float4*)(Cout + (size_t)row * ND4 + cbase + 4) = o1;
    }
}

// ---------------- fused recurrent step GEMM (both stacks, split-K) --------
// grid = 768: stack = bx&1; (bx>>1) = khalf*192 + coltile(64 cols).
// block = 256 = 8 warps; warp w = k-slice of 192 within its K-half,
// processed in 3 chunks of 64 k staged through smem.
// HALF-WARP B-SPLIT: lanes 0-15 handle b0-7, lanes 16-31 handle b8-15;
// each lane takes 4 consecutive cols. Per k per warp:
//   1 LDG.128 (R float4, 256B unique) + 2 LDS.128 (2-way bcast) + 16 FFMA2
// = 4 L1 wavefronts per 32 MACs (vs 6 in R11). acc = 16 u64 (same 32 regs),
// h in-flight halves -> target regs <= 72.
__global__ void __launch_bounds__(256) step_gemm_f(const float* __restrict__ R1,
                                                   const float* __restrict__ R2) {
    __shared__ float smem[8192];  // 32 KB: h-chunk stage, reused for reduction
    int bx = blockIdx.x;
    int s = bx & 1;
    int tmp = bx >> 1;          // 0..383
    int kh = tmp / 192;         // K-half
    int cb = tmp - kh * 192;    // col-tile 0..191
    const float* __restrict__ R = s ? R2 : R1;
    int tid = threadIdx.x;
    int ksl = tid >> 5;
    int l = tid & 31;
    int hw = l >> 4;            // b-half: 0 -> b0-7, 1 -> b8-15
    int lh = l & 15;
    int col0 = cb * 64 + lh * 4;

    // acc[c][p]: column c (0..3), b-pair p within this lane's b-half
    unsigned long long acc[4][4];
#pragma unroll
    for (int c = 0; c < 4; c++)
#pragma unroll
        for (int p = 0; p < 4; p++) acc[c][p] = 0ull;

    const float4* hT4 = (const float4*)(d_hT + s * ND * NB);

    for (int c0 = 0; c0 < 192; c0 += 64) {
        // stage hT chunk: layout [ksl][kk(64)][b(16)]
        // warp ksl covers k in [kh*1536 + ksl*192 + c0, +64)
#pragma unroll
        for (int i = 0; i < 8; i++) {
            int s4 = tid + i * 256;
            int ksl_l = s4 >> 8;
            int rem = s4 & 255;
            ((float4*)smem)[s4] = hT4[kh * 6144 + ksl_l * 768 + c0 * 4 + rem];
        }
        __syncthreads();

        const float* rp = R + (size_t)(kh * 1536 + ksl * 192 + c0) * ND4 + col0;
#pragma unroll 4
        for (int kk = 0; kk < 64; kk++) {
            float4 rv = __ldcs((const float4*)(rp + (size_t)kk * ND4));
            const ulonglong2* hp =
                (const ulonglong2*)(smem + ((ksl * 64 + kk) << 4) + (hw << 3));
            ulonglong2 hA = hp[0], hB = hp[1];  // 4 b-pairs of this half
            unsigned long long rr;
            rr = pack2(rv.x, rv.x);
            fma2(acc[0][0], rr, hA.x); fma2(acc[0][1], rr, hA.y);
            fma2(acc[0][2], rr, hB.x); fma2(acc[0][3], rr, hB.y);
            rr = pack2(rv.y, rv.y);
            fma2(acc[1][0], rr, hA.x); fma2(acc[1][1], rr, hA.y);
            fma2(acc[1][2], rr, hB.x); fma2(acc[1][3], rr, hB.y);
            rr = pack2(rv.z, rv.z);
            fma2(acc[2][0], rr, hA.x); fma2(acc[2][1], rr, hA.y);
            fma2(acc[2][2], rr, hB.x); fma2(acc[2][3], rr, hB.y);
            rr = pack2(rv.w, rv.w);
            fma2(acc[3][0], rr, hA.x); fma2(acc[3][1], rr, hA.y);
            fma2(acc[3][2], rr, hB.x); fma2(acc[3][3], rr, hB.y);
        }
        __syncthreads();
    }

    // write partials to smem: sa[ksl][col(64)][8 u64 = b0..b15 pairs]
    unsigned long long* sa = (unsigned long long*)smem;
#pragma unroll
    for (int c = 0; c < 4; c++) {
        int colL = lh * 4 + c;
#pragma unroll
        for (int p = 0; p < 4; p++)
            sa[(ksl * 64 + colL) * 8 + hw * 4 + p] = acc[c][p];
    }
    __syncthreads();

    // cross-slice reduction (identical shape to R11)
    if (tid < 64) {
        int colg = cb * 64 + tid;
        float* g = d_gTp + ((kh * 2 + s) * ND4 + colg) * NB;
#pragma unroll
        for (int j = 0; j < 8; j++) {
            float sx = 0.f, sy = 0.f;
#pragma unroll
            for (int sl = 0; sl < 8; sl++) {
                float2 v = unpack2(sa[(sl * 64 + tid) * 8 + j]);
                sx += v.x;
                sy += v.y;
            }
            *(float2*)(g + 2 * j) = make_float2(sx, sy);
        }
    }
}

// ---------------- fused sLSTM gate update (both stacks) ----------------
// thread = (stack, d, b-half of 8). g = gTp[0] + gTp[1] + pre[:,t,:];
// updates states, writes hT [stack][d][b] and Y [b][t][d].
__global__ void __launch_bounds__(256) gate_step_f(int t) {
    int idx = blockIdx.x * 256 + threadIdx.x;  // 12288 threads
    int s = idx / (2 * ND);
    int r = idx - s * (2 * ND);
    int d = r >> 1;
    int b0 = (r & 1) << 3;
    const float* __restrict__ pre = s ? d_pre2 : d_pre1;
    float* __restrict__ Y = s ? d_Y2 : d_Y1;

    const int rowstep = (ND * NB) / 4;   // float4 stride between gates
    const int half = (2 * ND4 * NB) / 4; // float4 stride between K-halves
    const float4* gi = (const float4*)(d_gTp + (s * ND4 + d) * NB + b0);

    float gv[4][8];
#pragma unroll
    for (int gt = 0; gt < 4; gt++) {
        float4 p0 = gi[gt * rowstep], p1 = gi[gt * rowstep + 1];
        float4 q0 = gi[gt * rowstep + half], q1 = gi[gt * rowstep + half + 1];
        gv[gt][0] = p0.x + q0.x; gv[gt][1] = p0.y + q0.y;
        gv[gt][2] = p0.z + q0.z; gv[gt][3] = p0.w + q0.w;
        gv[gt][4] = p1.x + q1.x; gv[gt][5] = p1.y + q1.y;
        gv[gt][6] = p1.z + q1.z; gv[gt][7] = p1.w + q1.w;
    }

    int sbase = (s * ND + d) * NB + b0;
    float4 c0 = *(const float4*)(d_cst + sbase);
    float4 c1 = *(const float4*)(d_cst + sbase + 4);
    float4 n0 = *(const float4*)(d_nst + sbase);
    float4 n1 = *(const float4*)(d_nst + sbase + 4);
    float4 m0 = *(const float4*)(d_mst + sbase);
    float4 m1 = *(const float4*)(d_mst + sbase + 4);
    float cv[8] = {c0.x, c0.y, c0.z, c0.w, c1.x, c1.y, c1.z, c1.w};
    float nv[8] = {n0.x, n0.y, n0.z, n0.w, n1.x, n1.y, n1.z, n1.w};
    float mv[8] = {m0.x, m0.y, m0.z, m0.w, m1.x, m1.y, m1.z, m1.w};
    float hv[8];

#pragma unroll
    for (int j = 0; j < 8; j++) {
        int b = b0 + j;
        const float* prow = pre + (size_t)(b * NT + t) * ND4 + d;
        float it = gv[0][j] + prow[0];
        float ft = gv[1][j] + prow[ND];
        float zt = gv[2][j] + prow[2 * ND];
        float ot = gv[3][j] + prow[3 * ND];
        float m = mv[j];
        float mn = fmaxf(ft + m, it);
        float ig = expf(it - mn);
        float fg = expf(ft + m - mn);
        float cn = fg * cv[j] + ig * tanhf(zt);
        float nn = fg * nv[j] + ig;
        float h = cn / (nn + 1e-6f) * (1.0f / (1.0f + expf(-ot)));
        cv[j] = cn;
        nv[j] = nn;
        mv[j] = mn;
        hv[j] = h;
        Y[(size_t)b * (NT * ND) + t * ND + d] = h;
    }

    *(float4*)(d_cst + sbase) = make_float4(cv[0], cv[1], cv[2], cv[3]);
    *(float4*)(d_cst + sbase + 4) = make_float4(cv[4], cv[5], cv[6], cv[7]);
    *(float4*)(d_nst + sbase) = make_float4(nv[0], nv[1], nv[2], nv[3]);
    *(float4*)(d_nst + sbase + 4) = make_float4(nv[4], nv[5], nv[6], nv[7]);
    *(float4*)(d_mst + sbase) = make_float4(mv[0], mv[1], mv[2], mv[3]);
    *(float4*)(d_mst + sbase + 4) = make_float4(mv[4], mv[5], mv[6], mv[7]);
    *(float4*)(d_hT + sbase) = make_float4(hv[0], hv[1], hv[2], hv[3]);
    *(float4*)(d_hT + sbase + 4) = make_float4(hv[4], hv[5], hv[6], hv[7]);
}

__global__ void init_state() {
    int idx = blockIdx.x * 256 + threadIdx.x;  // 98304
    d_cst[idx] = 0.f;
    d_nst[idx] = 0.f;
    d_mst[idx] = 0.f;
    d_hT[idx] = 0.f;
}

// ---------------- spatial means ----------------
// xh[b,c,p] = mean_q Y2[(b*64+c)*2304 + p*48 + q]   (contiguous)
// xw[b,c,p] = mean_q Y1[(b*64+c)*2304 + q*48 + p]   (strided)
__global__ void reduce_means() {
    int bc = blockIdx.x;  // 0..1023 = b*64+c
    int p = threadIdx.x;  // 0..47
    const float* base2 = d_Y2 + bc * 2304;
    const float* base1 = d_Y1 + bc * 2304;
    float s = 0.f;
#pragma unroll 8
    for (int q = 0; q < 48; q++) s += base2[p * 48 + q];
    d_xh[bc * 48 + p] = s * (1.0f / 48.0f);
    float s2 = 0.f;
#pragma unroll 8
    for (int q = 0; q < 48; q++) s2 += base1[q * 48 + p];
    d_xw[bc * 48 + p] = s2 * (1.0f / 48.0f);
}

// ---------------- grouped conv1d + GroupNorm + sigmoid ----------------
__global__ void conv_gn(const float* __restrict__ cw, const float* __restrict__ gamma,
                        const float* __restrict__ beta) {
    int z = blockIdx.y;
    const float* u = z ? d_xw : d_xh;
    float* o = z ? d_sw : d_sh;
    int bidx = blockIdx.x;
    int b = bidx >> 4, g = bidx & 15;
    __shared__ float uin[8][52];
    __shared__ float wsh[4][8][5];
    __shared__ float svals[192];
    __shared__ float stats[2];
    int tid = threadIdx.x;
    int cg = g >> 1;  // conv group of this GN group's channels

    for (int i = tid; i < 384; i += 192) {
        int ci = i / 48, p = i - ci * 48;
        uin[ci][p + 2] = u[(b * NC + cg * 8 + ci) * 48 + p];
    }
    if (tid < 8) {
        uin[tid][0] = 0.f;
        uin[tid][1] = 0.f;
        uin[tid][50] = 0.f;
        uin[tid][51] = 0.f;
    }
    for (int i = tid; i < 160; i += 192) {
        ((float*)wsh)[i] = cw[g * 160 + i];
    }
    __syncthreads();

    int lc = tid / 48, p = tid - lc * 48;
    float v = 0.f;
#pragma unroll
    for (int ci = 0; ci < 8; ci++)
#pragma unroll
        for (int k = 0; k < 5; k++) v += uin[ci][p + k] * wsh[lc][ci][k];

    svals[tid] = v;
    __syncthreads();
    if (tid < 32) {
        float s = 0.f, s2 = 0.f;
#pragma unroll
        for (int i = 0; i < 6; i++) {
            float x = svals[tid + i * 32];
            s += x;
            s2 += x * x;
        }
#pragma unroll
        for (int off = 16; off; off >>= 1) {
            s += __shfl_xor_sync(0xffffffff, s, off);
            s2 += __shfl_xor_sync(0xffffffff, s2, off);
        }
        if (tid == 0) {
            stats[0] = s * (1.0f / 192.0f);
            stats[1] = s2 * (1.0f / 192.0f);
        }
    }
    __syncthreads();
    float mu = stats[0];
    float var = stats[1] - mu * mu;
    int co = 4 * g + lc;
    float xn = (v - mu) * rsqrtf(var + 1e-5f);
    float yv = xn * gamma[co] + beta[co];
    o[(b * NC + co) * 48 + p] = 1.0f / (1.0f + expf(-yv));
}

// ---------------- final: out[b,c,h,w] = sh[b,c,h]*sw[b,c,w]*x ----------------
__global__ void final_mul(const float* __restrict__ x, float* __restrict__ out) {
    int idx = blockIdx.x * 256 + threadIdx.x;  // 2359296 total, exact
    int b = idx / (NC * NH * NH);
    int r = idx - b * (NC * NH * NH);
    int c = r / (NH * NH);
    int r2 = r - c * (NH * NH);
    int h = r2 / NH;
    int w = r2 - h * NH;
    out[idx] = d_sh[(b * NC + c) * 48 + h] * d_sw[(b * NC + c) * 48 + w] * x[idx];
}

// ---------------- launch ----------------
extern "C" void kernel_launch(void* const* d_in, const int* in_sizes, int n_in,
                              void* d_out, int out_size) {
    const float* x  = (const float*)d_in[0];
    const float* W1 = (const float*)d_in[1];
    const float* R1 = (const float*)d_in[2];
    const float* b1 = (const float*)d_in[3];
    const float* W2 = (const float*)d_in[4];
    const float* R2 = (const float*)d_in[5];
    const float* b2 = (const float*)d_in[6];
    const float* cw = (const float*)d_in[7];
    const float* gg = (const float*)d_in[8];
    const float* gb = (const float*)d_in[9];
    float* out = (float*)d_out;

    dim3 gpre(96, 6);
    sgemm_pre<<<gpre, 256>>>(x, W1, b1, 0);
    sgemm_pre<<<gpre, 256>>>(x, W2, b2, 1);

    init_state<<<384, 256>>>();
    for (int t = 0; t < NT; t++) {
        step_gemm_f<<<768, 256>>>(R1, R2);
        gate_step_f<<<48, 256>>>(t);
    }

    reduce_means<<<1024, 48>>>();
    conv_gn<<<dim3(256, 2), 192>>>(cw, gg, gb);
    final_mul<<<9216, 256>>>(x, out);
}

// round 13
// speedup vs baseline: 1.1139x; 1.1139x over previous
#include <cuda_runtime.h>
#include <cstdint>

// Problem constants
#define NB   16      // batch
#define NC   64      // channels
#define NH   48      // H == W
#define ND   3072    // xLSTM feature dim (C*W)
#define ND4  12288   // 4*D
#define NT   48      // sequence length
#define NROWS 768    // B*T

// step-GEMM tiling
#define KQ   12      // split-K factor
#define NCT  48      // column tiles of 256
#define CT   256     // cols per block
#define KT   16      // k per tile
#define NTILES 16    // (3072/KQ)/KT

// ---------------- device scratch (no allocations allowed) ----------------
__device__ float d_pre1[NROWS * ND4];        // 37.75 MB
__device__ float d_pre2[NROWS * ND4];        // 37.75 MB
__device__ float d_gTp[KQ * 2 * ND4 * NB];   // [kq][stack][col][b] partials, 18.9 MB
__device__ float d_cst[2 * ND * NB];         // [stack][d][b]
__device__ float d_nst[2 * ND * NB];
__device__ float d_mst[2 * ND * NB];
__device__ float d_hT[2 * ND * NB];          // [stack][d][b]
__device__ float d_Y1[NROWS * ND];           // hidden outputs stack 1 [b][t][d]
__device__ float d_Y2[NROWS * ND];           // hidden outputs stack 2
__device__ float d_xh[NB * NC * NH];
__device__ float d_xw[NB * NC * NH];
__device__ float d_sh[NB * NC * NH];
__device__ float d_sw[NB * NC * NH];

// ---------------- packed fp32x2 helpers (Blackwell FFMA2) ----------------
__device__ __forceinline__ unsigned long long pack2(float x, float y) {
    unsigned long long r;
    asm("mov.b64 %0, {%1, %2};" : "=l"(r) : "f"(x), "f"(y));
    return r;
}
__device__ __forceinline__ void fma2(unsigned long long& c, unsigned long long a,
                                     unsigned long long b) {
    asm("fma.rn.f32x2 %0, %1, %2, %0;" : "+l"(c) : "l"(a), "l"(b));
}
__device__ __forceinline__ float2 unpack2(unsigned long long v) {
    float2 f;
    asm("mov.b64 {%0, %1}, %2;" : "=f"(f.x), "=f"(f.y) : "l"(v));
    return f;
}

__device__ __forceinline__ uint32_t smem_u32(const void* p) {
    return (uint32_t)__cvta_generic_to_shared(p);
}
#define CP16(dst, src)                                                   \
    asm volatile("cp.async.cg.shared.global [%0], [%1], 16;" ::          \
                     "r"(dst), "l"(src))
#define CP_COMMIT() asm volatile("cp.async.commit_group;")
#define CP_WAIT1()  asm volatile("cp.async.wait_group 1;")
#define CP_WAIT0()  asm volatile("cp.async.wait_group 0;")

// ---------------- pre-projection GEMM: pre = X @ W + bias ----------------
// A: [768, 3072] (x viewed flat), W: [3072, 12288], out: [768, 12288]
// 128x128 tile, BK=8, 256 threads, 8x8 microtile via FFMA2.
__global__ void __launch_bounds__(256) sgemm_pre(const float* __restrict__ A,
                                                 const float* __restrict__ Wm,
                                                 const float* __restrict__ bias,
                                                 int which) {
    __shared__ float As[8][128];
    __shared__ float Bs[8][128];
    float* Cout = which ? d_pre2 : d_pre1;

    int tid = threadIdx.x;
    int bm = blockIdx.y, bn = blockIdx.x;
    int arow = tid >> 1, acol = (tid & 1) << 2;
    int brow = tid >> 5, bcol = (tid & 31) << 2;
    int ty = tid >> 4, tx = tid & 15;

    unsigned long long acc[8][4];
#pragma unroll
    for (int i = 0; i < 8; i++)
#pragma unroll
        for (int j = 0; j < 4; j++) acc[i][j] = 0ull;

    const float* Ap = A + (bm * 128 + arow) * ND + acol;
    const float* Bp = Wm + brow * ND4 + bn * 128 + bcol;

    for (int k0 = 0; k0 < ND; k0 += 8) {
        float4 av = *(const float4*)(Ap + k0);
        float4 bv = *(const float4*)(Bp + (size_t)k0 * ND4);
        As[acol + 0][arow] = av.x;
        As[acol + 1][arow] = av.y;
        As[acol + 2][arow] = av.z;
        As[acol + 3][arow] = av.w;
        *(float4*)&Bs[brow][bcol] = bv;
        __syncthreads();
#pragma unroll
        for (int kk = 0; kk < 8; kk++) {
            float4 a0 = *(const float4*)&As[kk][ty * 8];
            float4 a1 = *(const float4*)&As[kk][ty * 8 + 4];
            ulonglong2 bq0 = *(const ulonglong2*)&Bs[kk][tx * 8];
            ulonglong2 bq1 = *(const ulonglong2*)&Bs[kk][tx * 8 + 4];
            unsigned long long rb[4] = {bq0.x, bq0.y, bq1.x, bq1.y};
            float aa[8] = {a0.x, a0.y, a0.z, a0.w, a1.x, a1.y, a1.z, a1.w};
#pragma unroll
            for (int i = 0; i < 8; i++) {
                unsigned long long ra = pack2(aa[i], aa[i]);
#pragma unroll
                for (int j = 0; j < 4; j++) fma2(acc[i][j], ra, rb[j]);
            }
        }
        __syncthreads();
    }

    int cbase = bn * 128 + tx * 8;
    float4 bb0 = *(const float4*)(bias + cbase);
    float4 bb1 = *(const float4*)(bias + cbase + 4);
#pragma unroll
    for (int i = 0; i < 8; i++) {
        int row = bm * 128 + ty * 8 + i;
        float2 v0 = unpack2(acc[i][0]);
        float2 v1 = unpack2(acc[i][1]);
        float2 v2 = unpack2(acc[i][2]);
        float2 v3 = unpack2(acc[i][3]);
        float4 o0 = make_float4(v0.x + bb0.x, v0.y + bb0.y, v1.x + bb0.z, v1.y + bb0.w);
        float4 o1 = make_float4(v2.x + bb1.x, v2.y + bb1.y, v3.x + bb1.z, v3.y + bb1.w);
        *(float4*)(Cout + (size_t)row * ND4 + cbase) = o0;
        *(float4*)(Cout + (size_t)row * ND4 + cbase + 4) = o1;
    }
}

// ---------------- fused recurrent step GEMM: cp.async-pipelined ----------
// grid = 1152: stack = bx&1; (bx>>1) = kq*48 + ct. Block: 256 cols, 256 k.
// 2-stage smem pipeline (R 16KB + h 1KB per stage) filled by cp.async.cg;
// all warps share the tile; warps 0-3 take k rows 0-7, warps 4-7 rows 8-15.
// Lane microtile: 4 cols x one b-half (16 FFMA2 per k).
// Cross-group reduction via smem, coalesced 64B/col partial stores.
__global__ void __launch_bounds__(256, 4) step_gemm_f(const float* __restrict__ R1,
                                                      const float* __restrict__ R2) {
    __shared__ float smem[8704];  // 34 KB: RS[2][16][256] + HS[2][16][16]
    int bx = blockIdx.x;
    int s = bx & 1;
    int t2 = bx >> 1;           // 0..575
    int kq = t2 / NCT;          // 0..11
    int ct = t2 - kq * NCT;     // 0..47
    const float* __restrict__ R = s ? R2 : R1;
    int tid = threadIdx.x;
    int w = tid >> 5, l = tid & 31;
    int grp = w >> 2;           // k-subgroup: 0 -> rows 0-7, 1 -> rows 8-15
    int wc = (w & 3) * 64;      // warp's 64-col band
    int hw = l >> 4;            // b-half
    int lh = l & 15;
    int mycol = wc + lh * 4;
    int k0 = kq * 256;
    int colbase = ct * CT;

    // fill helpers (addresses precomputed per thread)
    int frow = tid >> 6;             // 0..3 (R fill, +4 per pass)
    int fcol = (tid & 63) * 4;       // float offset
    const float* rsrc = R + (size_t)(k0 + frow) * ND4 + colbase + fcol;
    float* rdst0 = smem + frow * 256 + fcol;
    int hrow = tid >> 2;             // h fill (tid<64)
    int hb4 = (tid & 3) * 4;
    const float* hsrc = d_hT + s * (ND * NB) + (k0 + hrow) * NB + hb4;
    float* hdst0 = smem + 8192 + hrow * 16 + hb4;

    unsigned long long acc[4][4];
#pragma unroll
    for (int c = 0; c < 4; c++)
#pragma unroll
        for (int p = 0; p < 4; p++) acc[c][p] = 0ull;

    // prologue: fill tile 0 into stage 0
    {
#pragma unroll
        for (int pass = 0; pass < 4; pass++)
            CP16(smem_u32(rdst0 + pass * 4 * 256), rsrc + (size_t)(pass * 4) * ND4);
        if (tid < 64) CP16(smem_u32(hdst0), hsrc);
        CP_COMMIT();
    }

#pragma unroll 1
    for (int i = 0; i < NTILES; i++) {
        int st = i & 1;
        if (i + 1 < NTILES) {
            int nst = (i + 1) & 1;
            const float* rs = rsrc + (size_t)((i + 1) * KT) * ND4;
            float* rd = rdst0 + nst * 4096;
#pragma unroll
            for (int pass = 0; pass < 4; pass++)
                CP16(smem_u32(rd + pass * 4 * 256), rs + (size_t)(pass * 4) * ND4);
            if (tid < 64)
                CP16(smem_u32(hdst0 + nst * 256), hsrc + (size_t)((i + 1) * KT) * NB);
            CP_COMMIT();
            CP_WAIT1();
        } else {
            CP_WAIT0();
        }
        __syncthreads();

        const float* rbase = smem + st * 4096 + grp * 8 * 256 + mycol;
        const float* hbase = smem + 8192 + st * 256 + grp * 8 * 16 + hw * 8;
#pragma unroll
        for (int kk = 0; kk < 8; kk++) {
            float4 rv = *(const float4*)(rbase + kk * 256);
            const ulonglong2* hp = (const ulonglong2*)(hbase + kk * 16);
            ulonglong2 hA = hp[0], hB = hp[1];
            unsigned long long rr;
            rr = pack2(rv.x, rv.x);
            fma2(acc[0][0], rr, hA.x); fma2(acc[0][1], rr, hA.y);
            fma2(acc[0][2], rr, hB.x); fma2(acc[0][3], rr, hB.y);
            rr = pack2(rv.y, rv.y);
            fma2(acc[1][0], rr, hA.x); fma2(acc[1][1], rr, hA.y);
            fma2(acc[1][2], rr, hB.x); fma2(acc[1][3], rr, hB.y);
            rr = pack2(rv.z, rv.z);
            fma2(acc[2][0], rr, hA.x); fma2(acc[2][1], rr, hA.y);
            fma2(acc[2][2], rr, hB.x); fma2(acc[2][3], rr, hB.y);
            rr = pack2(rv.w, rv.w);
            fma2(acc[3][0], rr, hA.x); fma2(acc[3][1], rr, hA.y);
            fma2(acc[3][2], rr, hB.x); fma2(acc[3][3], rr, hB.y);
        }
        __syncthreads();
    }

    // dump both k-subgroups' partials to smem: sa[grp][col][8 u64]
    unsigned long long* sa = (unsigned long long*)smem;
#pragma unroll
    for (int c = 0; c < 4; c++) {
        int col = wc + lh * 4 + c;
#pragma unroll
        for (int p = 0; p < 4; p++)
            sa[grp * 2048 + col * 8 + hw * 4 + p] = acc[c][p];
    }
    __syncthreads();

    // coalesced partial store: thread t owns column t (16 floats = 64B)
    {
        int col = tid;
        float out[16];
#pragma unroll
        for (int j = 0; j < 8; j++) {
            float2 va = unpack2(sa[col * 8 + j]);
            float2 vb = unpack2(sa[2048 + col * 8 + j]);
            out[2 * j] = va.x + vb.x;
            out[2 * j + 1] = va.y + vb.y;
        }
        float* g = d_gTp + ((size_t)(kq * 2 + s) * ND4 + colbase + col) * NB;
#pragma unroll
        for (int q = 0; q < 4; q++)
            *(float4*)(g + 4 * q) =
                make_float4(out[4 * q], out[4 * q + 1], out[4 * q + 2], out[4 * q + 3]);
    }
}

// ---------------- fused sLSTM gate update (both stacks) ----------------
// thread = (stack, d, b-half of 8). g = sum_kq gTp[kq] + pre[:,t,:];
// updates states, writes hT [stack][d][b] and Y [b][t][d].
__global__ void __launch_bounds__(256) gate_step_f(int t) {
    int idx = blockIdx.x * 256 + threadIdx.x;  // 12288 threads
    int s = idx / (2 * ND);
    int r = idx - s * (2 * ND);
    int d = r >> 1;
    int b0 = (r & 1) << 3;
    const float* __restrict__ pre = s ? d_pre2 : d_pre1;
    float* __restrict__ Y = s ? d_Y2 : d_Y1;

    const int rowstep = (ND * NB) / 4;      // float4 stride between gates
    const int qstride = (2 * ND4 * NB) / 4; // float4 stride between k-partials
    const float4* gi = (const float4*)(d_gTp + ((size_t)s * ND4 + d) * NB + b0);

    float gv[4][8];
#pragma unroll
    for (int gt = 0; gt < 4; gt++)
#pragma unroll
        for (int j = 0; j < 8; j++) gv[gt][j] = 0.f;

#pragma unroll
    for (int q = 0; q < KQ; q++) {
#pragma unroll
        for (int gt = 0; gt < 4; gt++) {
            float4 p0 = gi[q * qstride + gt * rowstep];
            float4 p1 = gi[q * qstride + gt * rowstep + 1];
            gv[gt][0] += p0.x; gv[gt][1] += p0.y;
            gv[gt][2] += p0.z; gv[gt][3] += p0.w;
            gv[gt][4] += p1.x; gv[gt][5] += p1.y;
            gv[gt][6] += p1.z; gv[gt][7] += p1.w;
        }
    }

    int sbase = (s * ND + d) * NB + b0;
    float4 c0 = *(const float4*)(d_cst + sbase);
    float4 c1 = *(const float4*)(d_cst + sbase + 4);
    float4 n0 = *(const float4*)(d_nst + sbase);
    float4 n1 = *(const float4*)(d_nst + sbase + 4);
    float4 m0 = *(const float4*)(d_mst + sbase);
    float4 m1 = *(const float4*)(d_mst + sbase + 4);
    float cv[8] = {c0.x, c0.y, c0.z, c0.w, c1.x, c1.y, c1.z, c1.w};
    float nv[8] = {n0.x, n0.y, n0.z, n0.w, n1.x, n1.y, n1.z, n1.w};
    float mv[8] = {m0.x, m0.y, m0.z, m0.w, m1.x, m1.y, m1.z, m1.w};
    float hv[8];

#pragma unroll
    for (int j = 0; j < 8; j++) {
        int b = b0 + j;
        const float* prow = pre + (size_t)(b * NT + t) * ND4 + d;
        float it = gv[0][j] + prow[0];
        float ft = gv[1][j] + prow[ND];
        float zt = gv[2][j] + prow[2 * ND];
        float ot = gv[3][j] + prow[3 * ND];
        float m = mv[j];
        float mn = fmaxf(ft + m, it);
        float ig = expf(it - mn);
        float fg = expf(ft + m - mn);
        float cn = fg * cv[j] + ig * tanhf(zt);
        float nn = fg * nv[j] + ig;
        float h = cn / (nn + 1e-6f) * (1.0f / (1.0f + expf(-ot)));
        cv[j] = cn;
        nv[j] = nn;
        mv[j] = mn;
        hv[j] = h;
        Y[(size_t)b * (NT * ND) + t * ND + d] = h;
    }

    *(float4*)(d_cst + sbase) = make_float4(cv[0], cv[1], cv[2], cv[3]);
    *(float4*)(d_cst + sbase + 4) = make_float4(cv[4], cv[5], cv[6], cv[7]);
    *(float4*)(d_nst + sbase) = make_float4(nv[0], nv[1], nv[2], nv[3]);
    *(float4*)(d_nst + sbase + 4) = make_float4(nv[4], nv[5], nv[6], nv[7]);
    *(float4*)(d_mst + sbase) = make_float4(mv[0], mv[1], mv[2], mv[3]);
    *(float4*)(d_mst + sbase + 4) = make_float4(mv[4], mv[5], mv[6], mv[7]);
    *(float4*)(d_hT + sbase) = make_float4(hv[0], hv[1], hv[2], hv[3]);
    *(float4*)(d_hT + sbase + 4) = make_float4(hv[4], hv[5], hv[6], hv[7]);
}

__global__ void init_state() {
    int idx = blockIdx.x * 256 + threadIdx.x;  // 98304
    d_cst[idx] = 0.f;
    d_nst[idx] = 0.f;
    d_mst[idx] = 0.f;
    d_hT[idx] = 0.f;
}

// ---------------- spatial means ----------------
// xh[b,c,p] = mean_q Y2[(b*64+c)*2304 + p*48 + q]   (contiguous)
// xw[b,c,p] = mean_q Y1[(b*64+c)*2304 + q*48 + p]   (strided)
__global__ void reduce_means() {
    int bc = blockIdx.x;  // 0..1023 = b*64+c
    int p = threadIdx.x;  // 0..47
    const float* base2 = d_Y2 + bc * 2304;
    const float* base1 = d_Y1 + bc * 2304;
    float s = 0.f;
#pragma unroll 8
    for (int q = 0; q < 48; q++) s += base2[p * 48 + q];
    d_xh[bc * 48 + p] = s * (1.0f / 48.0f);
    float s2 = 0.f;
#pragma unroll 8
    for (int q = 0; q < 48; q++) s2 += base1[q * 48 + p];
    d_xw[bc * 48 + p] = s2 * (1.0f / 48.0f);
}

// ---------------- grouped conv1d + GroupNorm + sigmoid ----------------
__global__ void conv_gn(const float* __restrict__ cw, const float* __restrict__ gamma,
                        const float* __restrict__ beta) {
    int z = blockIdx.y;
    const float* u = z ? d_xw : d_xh;
    float* o = z ? d_sw : d_sh;
    int bidx = blockIdx.x;
    int b = bidx >> 4, g = bidx & 15;
    __shared__ float uin[8][52];
    __shared__ float wsh[4][8][5];
    __shared__ float svals[192];
    __shared__ float stats[2];
    int tid = threadIdx.x;
    int cg = g >> 1;  // conv group of this GN group's channels

    for (int i = tid; i < 384; i += 192) {
        int ci = i / 48, p = i - ci * 48;
        uin[ci][p + 2] = u[(b * NC + cg * 8 + ci) * 48 + p];
    }
    if (tid < 8) {
        uin[tid][0] = 0.f;
        uin[tid][1] = 0.f;
        uin[tid][50] = 0.f;
        uin[tid][51] = 0.f;
    }
    for (int i = tid; i < 160; i += 192) {
        ((float*)wsh)[i] = cw[g * 160 + i];
    }
    __syncthreads();

    int lc = tid / 48, p = tid - lc * 48;
    float v = 0.f;
#pragma unroll
    for (int ci = 0; ci < 8; ci++)
#pragma unroll
        for (int k = 0; k < 5; k++) v += uin[ci][p + k] * wsh[lc][ci][k];

    svals[tid] = v;
    __syncthreads();
    if (tid < 32) {
        float s = 0.f, s2 = 0.f;
#pragma unroll
        for (int i = 0; i < 6; i++) {
            float x = svals[tid + i * 32];
            s += x;
            s2 += x * x;
        }
#pragma unroll
        for (int off = 16; off; off >>= 1) {
            s += __shfl_xor_sync(0xffffffff, s, off);
            s2 += __shfl_xor_sync(0xffffffff, s2, off);
        }
        if (tid == 0) {
            stats[0] = s * (1.0f / 192.0f);
            stats[1] = s2 * (1.0f / 192.0f);
        }
    }
    __syncthreads();
    float mu = stats[0];
    float var = stats[1] - mu * mu;
    int co = 4 * g + lc;
    float xn = (v - mu) * rsqrtf(var + 1e-5f);
    float yv = xn * gamma[co] + beta[co];
    o[(b * NC + co) * 48 + p] = 1.0f / (1.0f + expf(-yv));
}

// ---------------- final: out[b,c,h,w] = sh[b,c,h]*sw[b,c,w]*x ----------------
__global__ void final_mul(const float* __restrict__ x, float* __restrict__ out) {
    int idx = blockIdx.x * 256 + threadIdx.x;  // 2359296 total, exact
    int b = idx / (NC * NH * NH);
    int r = idx - b * (NC * NH * NH);
    int c = r / (NH * NH);
    int r2 = r - c * (NH * NH);
    int h = r2 / NH;
    int w = r2 - h * NH;
    out[idx] = d_sh[(b * NC + c) * 48 + h] * d_sw[(b * NC + c) * 48 + w] * x[idx];
}

// ---------------- launch ----------------
extern "C" void kernel_launch(void* const* d_in, const int* in_sizes, int n_in,
                              void* d_out, int out_size) {
    const float* x  = (const float*)d_in[0];
    const float* W1 = (const float*)d_in[1];
    const float* R1 = (const float*)d_in[2];
    const float* b1 = (const float*)d_in[3];
    const float* W2 = (const float*)d_in[4];
    const float* R2 = (const float*)d_in[5];
    const float* b2 = (const float*)d_in[6];
    const float* cw = (const float*)d_in[7];
    const float* gg = (const float*)d_in[8];
    const float* gb = (const float*)d_in[9];
    float* out = (float*)d_out;

    dim3 gpre(96, 6);
    sgemm_pre<<<gpre, 256>>>(x, W1, b1, 0);
    sgemm_pre<<<gpre, 256>>>(x, W2, b2, 1);

    init_state<<<384, 256>>>();
    for (int t = 0; t < NT; t++) {
        step_gemm_f<<<1152, 256>>>(R1, R2);
        gate_step_f<<<48, 256>>>(t);
    }

    reduce_means<<<1024, 48>>>();
    conv_gn<<<dim3(256, 2), 192>>>(cw, gg, gb);
    final_mul<<<9216, 256>>>(x, out);
}

// round 15
// speedup vs baseline: 1.3756x; 1.2350x over previous
#include <cuda_runtime.h>
#include <cuda_bf16.h>
#include <cstdint>

// Problem constants
#define NB   16      // batch
#define NC   64      // channels
#define NH   48      // H == W
#define ND   3072    // xLSTM feature dim (C*W)
#define ND4  12288   // 4*D
#define NT   48      // sequence length
#define NROWS 768    // B*T

// step-GEMM tiling
#define KQ   12      // split-K factor
#define NCT  48      // column tiles of 256
#define CT   256     // cols per block
#define KT   16      // k per tile
#define NTILES 16    // (3072/KQ)/KT

// ---------------- device scratch (no allocations allowed) ----------------
__device__ float d_pre1[NROWS * ND4];        // 37.75 MB
__device__ float d_pre2[NROWS * ND4];        // 37.75 MB
__device__ float d_gTp[KQ * 2 * ND4 * NB];   // [kq][stack][col][b] partials
__device__ float d_cst[2 * ND * NB];         // [stack][d][b]
__device__ float d_nst[2 * ND * NB];
__device__ float d_mst[2 * ND * NB];
__device__ float d_hT[2 * ND * NB];          // [stack][d][b]
__device__ float d_Y1[NROWS * ND];           // hidden outputs stack 1 [b][t][d]
__device__ float d_Y2[NROWS * ND];           // hidden outputs stack 2
__device__ float d_xh[NB * NC * NH];
__device__ float d_xw[NB * NC * NH];
__device__ float d_sh[NB * NC * NH];
__device__ float d_sw[NB * NC * NH];
// bf16 hi/lo split operands for tensor-core pre-GEMM
__device__ __nv_bfloat16 d_xhi[NROWS * ND];      // 4.7 MB
__device__ __nv_bfloat16 d_xlo[NROWS * ND];
__device__ __nv_bfloat16 d_W1hiT[ND4 * ND];      // 75.5 MB each (transposed [N,K])
__device__ __nv_bfloat16 d_W1loT[ND4 * ND];
__device__ __nv_bfloat16 d_W2hiT[ND4 * ND];
__device__ __nv_bfloat16 d_W2loT[ND4 * ND];

// ---------------- packed fp32x2 helpers (Blackwell FFMA2) ----------------
__device__ __forceinline__ unsigned long long pack2(float x, float y) {
    unsigned long long r;
    asm("mov.b64 %0, {%1, %2};" : "=l"(r) : "f"(x), "f"(y));
    return r;
}
__device__ __forceinline__ void fma2(unsigned long long& c, unsigned long long a,
                                     unsigned long long b) {
    asm("fma.rn.f32x2 %0, %1, %2, %0;" : "+l"(c) : "l"(a), "l"(b));
}
__device__ __forceinline__ float2 unpack2(unsigned long long v) {
    float2 f;
    asm("mov.b64 {%0, %1}, %2;" : "=f"(f.x), "=f"(f.y) : "l"(v));
    return f;
}

__device__ __forceinline__ uint32_t smem_u32(const void* p) {
    return (uint32_t)__cvta_generic_to_shared(p);
}
#define CP16(dst, src)                                                   \
    asm volatile("cp.async.cg.shared.global [%0], [%1], 16;" ::          \
                     "r"(dst), "l"(src))
#define CP_COMMIT() asm volatile("cp.async.commit_group;")
#define CP_WAIT1()  asm volatile("cp.async.wait_group 1;")
#define CP_WAIT0()  asm volatile("cp.async.wait_group 0;")

// ---------------- mma.sync / ldmatrix (baseline PTX, HMMA path) ----------
#define LDSM4(r0, r1, r2, r3, addr)                                      \
    asm volatile("ldmatrix.sync.aligned.m8n8.x4.shared.b16 "             \
                 "{%0,%1,%2,%3}, [%4];"                                  \
                 : "=r"(r0), "=r"(r1), "=r"(r2), "=r"(r3) : "r"(addr))
#define MMA16816(d, a, b0, b1)                                           \
    asm volatile("mma.sync.aligned.m16n8k16.row.col.f32.bf16.bf16.f32 "  \
                 "{%0,%1,%2,%3}, {%4,%5,%6,%7}, {%8,%9}, {%0,%1,%2,%3};" \
                 : "+f"((d)[0]), "+f"((d)[1]), "+f"((d)[2]), "+f"((d)[3]) \
                 : "r"((a)[0]), "r"((a)[1]), "r"((a)[2]), "r"((a)[3]),    \
                   "r"(b0), "r"(b1))

// ---------------- conversion kernels ----------------
// x fp32 -> xhi/xlo bf16 (hi/lo residual split)
__global__ void conv_x(const float* __restrict__ x) {
    int idx = blockIdx.x * 256 + threadIdx.x;  // 2359296 exact
    float v = x[idx];
    __nv_bfloat16 hi = __float2bfloat16(v);
    d_xhi[idx] = hi;
    d_xlo[idx] = __float2bfloat16(v - __bfloat162float(hi));
}

// W [K=3072, N=12288] fp32 -> WT hi/lo bf16 [N, K] (transposed)
__global__ void conv_WT(const float* __restrict__ W,
                        __nv_bfloat16* __restrict__ hiT,
                        __nv_bfloat16* __restrict__ loT) {
    __shared__ float t[32][33];
    int nb = blockIdx.x * 32, kb = blockIdx.y * 32;
    int tx = threadIdx.x, ty = threadIdx.y;
#pragma unroll
    for (int j = 0; j < 4; j++)
        t[ty + 8 * j][tx] = W[(size_t)(kb + ty + 8 * j) * ND4 + nb + tx];
    __syncthreads();
#pragma unroll
    for (int j = 0; j < 4; j++) {
        float v = t[tx][ty + 8 * j];
        __nv_bfloat16 hi = __float2bfloat16(v);
        size_t o = (size_t)(nb + ty + 8 * j) * ND + kb + tx;
        hiT[o] = hi;
        loT[o] = __float2bfloat16(v - __bfloat162float(hi));
    }
}

// ---------------- HMMA pre-projection: pre = X @ W + bias ----------------
// 3-term bf16 split as K-stack of 288 BK=32 chunks:
//   seg0: xhi @ WhiT, seg1: xhi @ WloT, seg2: xlo @ WhiT
// Tile 128x128, BK=32 bf16, 256 thr = 8 warps (warp: 32m x 64n).
// cp.async double-buffered smem, 80B padded rows (ldmatrix conflict-free).
// mma.sync m16n8k16 bf16 -> fp32; epilogue adds bias, stores fp32.
#define PSTRIDE 80       // padded row bytes (40 bf16)
#define PTILEB  10240    // 128 * 80
__global__ void __launch_bounds__(256) mma_pre(
    const __nv_bfloat16* __restrict__ BhiT,
    const __nv_bfloat16* __restrict__ BloT,
    const float* __restrict__ bias, int which) {
    __shared__ __align__(16) char smA[2][PTILEB];
    __shared__ __align__(16) char smB[2][PTILEB];
    __shared__ float biasS[128];

    int tid = threadIdx.x;
    int wid = tid >> 5, lane = tid & 31;
    int mbase = blockIdx.x * 128;
    int nbase = blockIdx.y * 128;
    float* Cout = which ? d_pre2 : d_pre1;
    int wm = (wid & 3) * 32;
    int wn = (wid >> 2) * 64;

    if (tid < 128) biasS[tid] = bias[nbase + tid];

    // fill assignment: 512 16B-chunks per matrix; thread does 2 each
    int row0 = tid >> 2, ch0 = tid & 3;          // idx = tid
    int row1 = (tid + 256) >> 2, ch1 = tid & 3;  // idx = tid+256

    float d[2][8][4];
#pragma unroll
    for (int mt = 0; mt < 2; mt++)
#pragma unroll
        for (int nt = 0; nt < 8; nt++)
#pragma unroll
            for (int q = 0; q < 4; q++) d[mt][nt][q] = 0.f;

    // prologue: fill stage 0 (chunk 0 = seg0, ko=0)
    {
        uint32_t da = smem_u32(smA[0]), db = smem_u32(smB[0]);
        CP16(da + row0 * PSTRIDE + ch0 * 16,
             d_xhi + (size_t)(mbase + row0) * ND + ch0 * 8);
        CP16(da + row1 * PSTRIDE + ch1 * 16,
             d_xhi + (size_t)(mbase + row1) * ND + ch1 * 8);
        CP16(db + row0 * PSTRIDE + ch0 * 16,
             BhiT + (size_t)(nbase + row0) * ND + ch0 * 8);
        CP16(db + row1 * PSTRIDE + ch1 * 16,
             BhiT + (size_t)(nbase + row1) * ND + ch1 * 8);
        CP_COMMIT();
    }

    int lrow = lane & 15, lcol = lane >> 4;

#pragma unroll 1
    for (int c = 0; c < 288; c++) {
        int st = c & 1;
        if (c + 1 < 288) {
            int nc = c + 1;
            int nst = nc & 1;
            int seg = nc / 96;
            int ko = (nc - seg * 96) * 32;
            const __nv_bfloat16 *As, *Bs;
            if (seg == 0) { As = d_xhi; Bs = BhiT; }
            else if (seg == 1) { As = d_xhi; Bs = BloT; }
            else { As = d_xlo; Bs = BhiT; }
            uint32_t da = smem_u32(smA[nst]), db = smem_u32(smB[nst]);
            CP16(da + row0 * PSTRIDE + ch0 * 16,
                 As + (size_t)(mbase + row0) * ND + ko + ch0 * 8);
            CP16(da + row1 * PSTRIDE + ch1 * 16,
                 As + (size_t)(mbase + row1) * ND + ko + ch1 * 8);
            CP16(db + row0 * PSTRIDE + ch0 * 16,
                 Bs + (size_t)(nbase + row0) * ND + ko + ch0 * 8);
            CP16(db + row1 * PSTRIDE + ch1 * 16,
                 Bs + (size_t)(nbase + row1) * ND + ko + ch1 * 8);
            CP_COMMIT();
            CP_WAIT1();
        } else {
            CP_WAIT0();
        }
        __syncthreads();

        uint32_t baseA = smem_u32(smA[st]);
        uint32_t baseB = smem_u32(smB[st]);
#pragma unroll
        for (int ks = 0; ks < 2; ks++) {
            uint32_t a[2][4];
#pragma unroll
            for (int mt = 0; mt < 2; mt++)
                LDSM4(a[mt][0], a[mt][1], a[mt][2], a[mt][3],
                      baseA + (wm + mt * 16 + lrow) * PSTRIDE + ks * 32 + lcol * 16);
            uint32_t b[4][4];
#pragma unroll
            for (int p = 0; p < 4; p++)
                LDSM4(b[p][0], b[p][1], b[p][2], b[p][3],
                      baseB + (wn + p * 16 + lrow) * PSTRIDE + ks * 32 + lcol * 16);
#pragma unroll
            for (int mt = 0; mt < 2; mt++)
#pragma unroll
                for (int p = 0; p < 4; p++) {
                    MMA16816(d[mt][2 * p], a[mt], b[p][0], b[p][2]);
                    MMA16816(d[mt][2 * p + 1], a[mt], b[p][1], b[p][3]);
                }
        }
        __syncthreads();
    }

    // epilogue: m16n8 D layout: d0,d1 -> (row lane/4, col (lane%4)*2);
    // d2,d3 -> row+8. Add bias, store fp32.
    int rb = mbase + wm + (lane >> 2);
    int cb = (lane & 3) * 2;
#pragma unroll
    for (int mt = 0; mt < 2; mt++) {
#pragma unroll
        for (int nt = 0; nt < 8; nt++) {
            int col = wn + nt * 8 + cb;
            float b0 = biasS[col], b1 = biasS[col + 1];
            int row = rb + mt * 16;
            *(float2*)(Cout + (size_t)row * ND4 + nbase + col) =
                make_float2(d[mt][nt][0] + b0, d[mt][nt][1] + b1);
            *(float2*)(Cout + (size_t)(row + 8) * ND4 + nbase + col) =
                make_float2(d[mt][nt][2] + b0, d[mt][nt][3] + b1);
        }
    }
}

// ---------------- fused recurrent step GEMM: cp.async-pipelined ----------
// (unchanged from R13: 74.9us measured)
__global__ void __launch_bounds__(256, 4) step_gemm_f(const float* __restrict__ R1,
                                                      const float* __restrict__ R2) {
    __shared__ float smem[8704];  // 34 KB: RS[2][16][256] + HS[2][16][16]
    int bx = blockIdx.x;
    int s = bx & 1;
    int t2 = bx >> 1;           // 0..575
    int kq = t2 / NCT;          // 0..11
    int ct = t2 - kq * NCT;     // 0..47
    const float* __restrict__ R = s ? R2 : R1;
    int tid = threadIdx.x;
    int w = tid >> 5, l = tid & 31;
    int grp = w >> 2;           // k-subgroup
    int wc = (w & 3) * 64;      // warp's 64-col band
    int hw = l >> 4;            // b-half
    int lh = l & 15;
    int mycol = wc + lh * 4;
    int k0 = kq * 256;
    int colbase = ct * CT;

    int frow = tid >> 6;
    int fcol = (tid & 63) * 4;
    const float* rsrc = R + (size_t)(k0 + frow) * ND4 + colbase + fcol;
    float* rdst0 = smem + frow * 256 + fcol;
    int hrow = tid >> 2;
    int hb4 = (tid & 3) * 4;
    const float* hsrc = d_hT + s * (ND * NB) + (k0 + hrow) * NB + hb4;
    float* hdst0 = smem + 8192 + hrow * 16 + hb4;

    unsigned long long acc[4][4];
#pragma unroll
    for (int c = 0; c < 4; c++)
#pragma unroll
        for (int p = 0; p < 4; p++) acc[c][p] = 0ull;

    {
#pragma unroll
        for (int pass = 0; pass < 4; pass++)
            CP16(smem_u32(rdst0 + pass * 4 * 256), rsrc + (size_t)(pass * 4) * ND4);
        if (tid < 64) CP16(smem_u32(hdst0), hsrc);
        CP_COMMIT();
    }

#pragma unroll 1
    for (int i = 0; i < NTILES; i++) {
        int st = i & 1;
        if (i + 1 < NTILES) {
            int nst = (i + 1) & 1;
            const float* rs = rsrc + (size_t)((i + 1) * KT) * ND4;
            float* rd = rdst0 + nst * 4096;
#pragma unroll
            for (int pass = 0; pass < 4; pass++)
                CP16(smem_u32(rd + pass * 4 * 256), rs + (size_t)(pass * 4) * ND4);
            if (tid < 64)
                CP16(smem_u32(hdst0 + nst * 256), hsrc + (size_t)((i + 1) * KT) * NB);
            CP_COMMIT();
            CP_WAIT1();
        } else {
            CP_WAIT0();
        }
        __syncthreads();

        const float* rbase = smem + st * 4096 + grp * 8 * 256 + mycol;
        const float* hbase = smem + 8192 + st * 256 + grp * 8 * 16 + hw * 8;
#pragma unroll
        for (int kk = 0; kk < 8; kk++) {
            float4 rv = *(const float4*)(rbase + kk * 256);
            const ulonglong2* hp = (const ulonglong2*)(hbase + kk * 16);
            ulonglong2 hA = hp[0], hB = hp[1];
            unsigned long long rr;
            rr = pack2(rv.x, rv.x);
            fma2(acc[0][0], rr, hA.x); fma2(acc[0][1], rr, hA.y);
            fma2(acc[0][2], rr, hB.x); fma2(acc[0][3], rr, hB.y);
            rr = pack2(rv.y, rv.y);
            fma2(acc[1][0], rr, hA.x); fma2(acc[1][1], rr, hA.y);
            fma2(acc[1][2], rr, hB.x); fma2(acc[1][3], rr, hB.y);
            rr = pack2(rv.z, rv.z);
            fma2(acc[2][0], rr, hA.x); fma2(acc[2][1], rr, hA.y);
            fma2(acc[2][2], rr, hB.x); fma2(acc[2][3], rr, hB.y);
            rr = pack2(rv.w, rv.w);
            fma2(acc[3][0], rr, hA.x); fma2(acc[3][1], rr, hA.y);
            fma2(acc[3][2], rr, hB.x); fma2(acc[3][3], rr, hB.y);
        }
        __syncthreads();
    }

    unsigned long long* sa = (unsigned long long*)smem;
#pragma unroll
    for (int c = 0; c < 4; c++) {
        int col = wc + lh * 4 + c;
#pragma unroll
        for (int p = 0; p < 4; p++)
            sa[grp * 2048 + col * 8 + hw * 4 + p] = acc[c][p];
    }
    __syncthreads();

    {
        int col = tid;
        float out[16];
#pragma unroll
        for (int j = 0; j < 8; j++) {
            float2 va = unpack2(sa[col * 8 + j]);
            float2 vb = unpack2(sa[2048 + col * 8 + j]);
            out[2 * j] = va.x + vb.x;
            out[2 * j + 1] = va.y + vb.y;
        }
        float* g = d_gTp + ((size_t)(kq * 2 + s) * ND4 + colbase + col) * NB;
#pragma unroll
        for (int q = 0; q < 4; q++)
            *(float4*)(g + 4 * q) =
                make_float4(out[4 * q], out[4 * q + 1], out[4 * q + 2], out[4 * q + 3]);
    }
}

// ---------------- fused sLSTM gate update (both stacks) ----------------
__global__ void __launch_bounds__(256) gate_step_f(int t) {
    int idx = blockIdx.x * 256 + threadIdx.x;  // 12288 threads
    int s = idx / (2 * ND);
    int r = idx - s * (2 * ND);
    int d = r >> 1;
    int b0 = (r & 1) << 3;
    const float* __restrict__ pre = s ? d_pre2 : d_pre1;
    float* __restrict__ Y = s ? d_Y2 : d_Y1;

    const int rowstep = (ND * NB) / 4;
    const int qstride = (2 * ND4 * NB) / 4;
    const float4* gi = (const float4*)(d_gTp + ((size_t)s * ND4 + d) * NB + b0);

    float gv[4][8];
#pragma unroll
    for (int gt = 0; gt < 4; gt++)
#pragma unroll
        for (int j = 0; j < 8; j++) gv[gt][j] = 0.f;

#pragma unroll
    for (int q = 0; q < KQ; q++) {
#pragma unroll
        for (int gt = 0; gt < 4; gt++) {
            float4 p0 = gi[q * qstride + gt * rowstep];
            float4 p1 = gi[q * qstride + gt * rowstep + 1];
            gv[gt][0] += p0.x; gv[gt][1] += p0.y;
            gv[gt][2] += p0.z; gv[gt][3] += p0.w;
            gv[gt][4] += p1.x; gv[gt][5] += p1.y;
            gv[gt][6] += p1.z; gv[gt][7] += p1.w;
        }
    }

    int sbase = (s * ND + d) * NB + b0;
    float4 c0 = *(const float4*)(d_cst + sbase);
    float4 c1 = *(const float4*)(d_cst + sbase + 4);
    float4 n0 = *(const float4*)(d_nst + sbase);
    float4 n1 = *(const float4*)(d_nst + sbase + 4);
    float4 m0 = *(const float4*)(d_mst + sbase);
    float4 m1 = *(const float4*)(d_mst + sbase + 4);
    float cv[8] = {c0.x, c0.y, c0.z, c0.w, c1.x, c1.y, c1.z, c1.w};
    float nv[8] = {n0.x, n0.y, n0.z, n0.w, n1.x, n1.y, n1.z, n1.w};
    float mv[8] = {m0.x, m0.y, m0.z, m0.w, m1.x, m1.y, m1.z, m1.w};
    float hv[8];

#pragma unroll
    for (int j = 0; j < 8; j++) {
        int b = b0 + j;
        const float* prow = pre + (size_t)(b * NT + t) * ND4 + d;
        float it = gv[0][j] + prow[0];
        float ft = gv[1][j] + prow[ND];
        float zt = gv[2][j] + prow[2 * ND];
        float ot = gv[3][j] + prow[3 * ND];
        float m = mv[j];
        float mn = fmaxf(ft + m, it);
        float ig = expf(it - mn);
        float fg = expf(ft + m - mn);
        float cn = fg * cv[j] + ig * tanhf(zt);
        float nn = fg * nv[j] + ig;
        float h = cn / (nn + 1e-6f) * (1.0f / (1.0f + expf(-ot)));
        cv[j] = cn;
        nv[j] = nn;
        mv[j] = mn;
        hv[j] = h;
        Y[(size_t)b * (NT * ND) + t * ND + d] = h;
    }

    *(float4*)(d_cst + sbase) = make_float4(cv[0], cv[1], cv[2], cv[3]);
    *(float4*)(d_cst + sbase + 4) = make_float4(cv[4], cv[5], cv[6], cv[7]);
    *(float4*)(d_nst + sbase) = make_float4(nv[0], nv[1], nv[2], nv[3]);
    *(float4*)(d_nst + sbase + 4) = make_float4(nv[4], nv[5], nv[6], nv[7]);
    *(float4*)(d_mst + sbase) = make_float4(mv[0], mv[1], mv[2], mv[3]);
    *(float4*)(d_mst + sbase + 4) = make_float4(mv[4], mv[5], mv[6], mv[7]);
    *(float4*)(d_hT + sbase) = make_float4(hv[0], hv[1], hv[2], hv[3]);
    *(float4*)(d_hT + sbase + 4) = make_float4(hv[4], hv[5], hv[6], hv[7]);
}

__global__ void init_state() {
    int idx = blockIdx.x * 256 + threadIdx.x;  // 98304
    d_cst[idx] = 0.f;
    d_nst[idx] = 0.f;
    d_mst[idx] = 0.f;
    d_hT[idx] = 0.f;
}

// ---------------- spatial means ----------------
__global__ void reduce_means() {
    int bc = blockIdx.x;  // 0..1023 = b*64+c
    int p = threadIdx.x;  // 0..47
    const float* base2 = d_Y2 + bc * 2304;
    const float* base1 = d_Y1 + bc * 2304;
    float s = 0.f;
#pragma unroll 8
    for (int q = 0; q < 48; q++) s += base2[p * 48 + q];
    d_xh[bc * 48 + p] = s * (1.0f / 48.0f);
    float s2 = 0.f;
#pragma unroll 8
    for (int q = 0; q < 48; q++) s2 += base1[q * 48 + p];
    d_xw[bc * 48 + p] = s2 * (1.0f / 48.0f);
}

// ---------------- grouped conv1d + GroupNorm + sigmoid ----------------
__global__ void conv_gn(const float* __restrict__ cw, const float* __restrict__ gamma,
                        const float* __restrict__ beta) {
    int z = blockIdx.y;
    const float* u = z ? d_xw : d_xh;
    float* o = z ? d_sw : d_sh;
    int bidx = blockIdx.x;
    int b = bidx >> 4, g = bidx & 15;
    __shared__ float uin[8][52];
    __shared__ float wsh[4][8][5];
    __shared__ float svals[192];
    __shared__ float stats[2];
    int tid = threadIdx.x;
    int cg = g >> 1;

    for (int i = tid; i < 384; i += 192) {
        int ci = i / 48, p = i - ci * 48;
        uin[ci][p + 2] = u[(b * NC + cg * 8 + ci) * 48 + p];
    }
    if (tid < 8) {
        uin[tid][0] = 0.f;
        uin[tid][1] = 0.f;
        uin[tid][50] = 0.f;
        uin[tid][51] = 0.f;
    }
    for (int i = tid; i < 160; i += 192) {
        ((float*)wsh)[i] = cw[g * 160 + i];
    }
    __syncthreads();

    int lc = tid / 48, p = tid - lc * 48;
    float v = 0.f;
#pragma unroll
    for (int ci = 0; ci < 8; ci++)
#pragma unroll
        for (int k = 0; k < 5; k++) v += uin[ci][p + k] * wsh[lc][ci][k];

    svals[tid] = v;
    __syncthreads();
    if (tid < 32) {
        float s = 0.f, s2 = 0.f;
#pragma unroll
        for (int i = 0; i < 6; i++) {
            float x = svals[tid + i * 32];
            s += x;
            s2 += x * x;
        }
#pragma unroll
        for (int off = 16; off; off >>= 1) {
            s += __shfl_xor_sync(0xffffffff, s, off);
            s2 += __shfl_xor_sync(0xffffffff, s2, off);
        }
        if (tid == 0) {
            stats[0] = s * (1.0f / 192.0f);
            stats[1] = s2 * (1.0f / 192.0f);
        }
    }
    __syncthreads();
    float mu = stats[0];
    float var = stats[1] - mu * mu;
    int co = 4 * g + lc;
    float xn = (v - mu) * rsqrtf(var + 1e-5f);
    float yv = xn * gamma[co] + beta[co];
    o[(b * NC + co) * 48 + p] = 1.0f / (1.0f + expf(-yv));
}

// ---------------- final: out[b,c,h,w] = sh[b,c,h]*sw[b,c,w]*x ----------------
__global__ void final_mul(const float* __restrict__ x, float* __restrict__ out) {
    int idx = blockIdx.x * 256 + threadIdx.x;  // 2359296 total, exact
    int b = idx / (NC * NH * NH);
    int r = idx - b * (NC * NH * NH);
    int c = r / (NH * NH);
    int r2 = r - c * (NH * NH);
    int h = r2 / NH;
    int w = r2 - h * NH;
    out[idx] = d_sh[(b * NC + c) * 48 + h] * d_sw[(b * NC + c) * 48 + w] * x[idx];
}

// ---------------- launch ----------------
extern "C" void kernel_launch(void* const* d_in, const int* in_sizes, int n_in,
                              void* d_out, int out_size) {
    const float* x  = (const float*)d_in[0];
    const float* W1 = (const float*)d_in[1];
    const float* R1 = (const float*)d_in[2];
    const float* b1 = (const float*)d_in[3];
    const float* W2 = (const float*)d_in[4];
    const float* R2 = (const float*)d_in[5];
    const float* b2 = (const float*)d_in[6];
    const float* cw = (const float*)d_in[7];
    const float* gg = (const float*)d_in[8];
    const float* gb = (const float*)d_in[9];
    float* out = (float*)d_out;

    // bf16 hi/lo conversion for tensor-core (HMMA) pre-GEMM
    conv_x<<<9216, 256>>>(x);
    __nv_bfloat16 *w1h, *w1l, *w2h, *w2l;
    cudaGetSymbolAddress((void**)&w1h, d_W1hiT);
    cudaGetSymbolAddress((void**)&w1l, d_W1loT);
    cudaGetSymbolAddress((void**)&w2h, d_W2hiT);
    cudaGetSymbolAddress((void**)&w2l, d_W2loT);
    conv_WT<<<dim3(384, 96), dim3(32, 8)>>>(W1, w1h, w1l);
    conv_WT<<<dim3(384, 96), dim3(32, 8)>>>(W2, w2h, w2l);

    mma_pre<<<dim3(6, 96), 256>>>(w1h, w1l, b1, 0);
    mma_pre<<<dim3(6, 96), 256>>>(w2h, w2l, b2, 1);

    init_state<<<384, 256>>>();
    for (int t = 0; t < NT; t++) {
        step_gemm_f<<<1152, 256>>>(R1, R2);
        gate_step_f<<<48, 256>>>(t);
    }

    reduce_means<<<1024, 48>>>();
    conv_gn<<<dim3(256, 2), 192>>>(cw, gg, gb);
    final_mul<<<9216, 256>>>(x, out);
}